// round 15
// baseline (speedup 1.0000x reference)
#include <cuda_runtime.h>
#include <cuda_bf16.h>
#include <stdint.h>
#include <math.h>

#define N_NODES 50000
#define N_EDGES 320000
#define HID 128
#define HEADS 4
#define N_LAYERS 2
#define SCAN_BLOCKS 196   // ceil(50000/256)

// ---------------- scratch (device globals; no allocations allowed) ----------
static __device__ __align__(16) float g_h[N_NODES * HID];
static __device__ __align__(16) float g_q[N_NODES * HID];
static __device__ __align__(16) float g_k[N_NODES * HID];
static __device__ __align__(16) float g_v[N_NODES * HID];
static __device__ __align__(16) float g_xr[N_NODES * HID];
static __device__ __align__(16) float g_hnew[N_NODES * HID];
static __device__ __align__(16) float g_bnsum[HID];
static __device__ __align__(16) float g_bnsq[HID];
static __device__ __align__(16) float g_scale[HID];
static __device__ __align__(16) float g_bias[HID];
static __device__ int g_idx64;
// CSR (edges grouped by target), built once per launch
static __device__ int g_deg[N_NODES];
static __device__ int g_cursor[N_NODES];
static __device__ int g_rowptr[N_NODES + 1];
static __device__ int g_csrc[N_EDGES];
static __device__ int g_ctgt[N_EDGES];
static __device__ float g_cea[N_EDGES];
static __device__ int g_bsum[SCAN_BLOCKS];
static __device__ int g_boff[SCAN_BLOCKS];
// attention scores, head-major planes [HEADS][N_EDGES]; read-only after alpha
static __device__ float g_alpha[HEADS * N_EDGES];
// bf16 hi/lo splits of the GEMM A operand (x, then h per layer)
static __device__ __align__(16) __nv_bfloat16 g_ahi[N_NODES * HID];
static __device__ __align__(16) __nv_bfloat16 g_alo[N_NODES * HID];
// bf16 hi/lo splits of transposed weights: [9][128 n][128 k]
static __device__ __align__(16) __nv_bfloat16 g_whi[9 * HID * HID];
static __device__ __align__(16) __nv_bfloat16 g_wlo[9 * HID * HID];

// ---------------- helpers ----------------------------------------------------
__device__ __forceinline__ long long load_idx(const void* ei, long long i) {
    return g_idx64 ? ((const long long*)ei)[i] : (long long)((const int*)ei)[i];
}
__device__ __forceinline__ int clamp_node(long long v) {
    int x = (int)v;
    if (x < 0) x = 0;
    if (x >= N_NODES) x = N_NODES - 1;
    return x;
}

// ---------------- fused weight split (all 9 mats) + idx detect + deg zero ----
__global__ __launch_bounds__(256) void wsplit_all_kernel(
    const float* __restrict__ W_in, const float* __restrict__ Wq,
    const float* __restrict__ Wk, const float* __restrict__ Wv,
    const float* __restrict__ Wskip, const void* __restrict__ ei)
{
    if (blockIdx.x == 0 && threadIdx.x == 0) {
        const int* p = (const int*)ei;
        int all0 = 1;
        for (int i = 0; i < 32; i++)
            if (p[2 * i + 1] != 0) { all0 = 0; break; }
        g_idx64 = all0;
    }
    int gi = blockIdx.x * 256 + threadIdx.x;
    if (gi < N_NODES) g_deg[gi] = 0;

    const int slot = blockIdx.x >> 6;
    const int idx = (blockIdx.x & 63) * 256 + threadIdx.x;
    if (idx >= HID * HID) return;
    const float* src;
    if (slot == 0) src = W_in;
    else {
        int l = (slot - 1) >> 2, m = (slot - 1) & 3;
        const float* bases[4] = {Wq, Wk, Wv, Wskip};
        src = bases[m] + (size_t)l * HID * HID;
    }
    int n = idx >> 7, k = idx & 127;
    float v = src[k * HID + n];
    __nv_bfloat16 hi = __float2bfloat16(v);
    float lo = v - __bfloat162float(hi);
    size_t o = (size_t)slot * HID * HID + idx;
    g_whi[o] = hi;
    g_wlo[o] = __float2bfloat16(lo);
}

__global__ __launch_bounds__(256) void xsplit_kernel(const float* __restrict__ x)
{
    int i = blockIdx.x * blockDim.x + threadIdx.x;
    if (i >= N_NODES * (HID / 4)) return;
    float4 v = *(const float4*)(x + (size_t)i * 4);
    __nv_bfloat162 h0 = __floats2bfloat162_rn(v.x, v.y);
    __nv_bfloat162 h1 = __floats2bfloat162_rn(v.z, v.w);
    __nv_bfloat162 l0 = __floats2bfloat162_rn(v.x - __bfloat162float(h0.x),
                                              v.y - __bfloat162float(h0.y));
    __nv_bfloat162 l1 = __floats2bfloat162_rn(v.z - __bfloat162float(h1.x),
                                              v.w - __bfloat162float(h1.y));
    ((__nv_bfloat162*)g_ahi)[i * 2 + 0] = h0;
    ((__nv_bfloat162*)g_ahi)[i * 2 + 1] = h1;
    ((__nv_bfloat162*)g_alo)[i * 2 + 0] = l0;
    ((__nv_bfloat162*)g_alo)[i * 2 + 1] = l1;
}

// ---------------- CSR build (two-level scan) ---------------------------------
__global__ __launch_bounds__(256) void csr_count_kernel(const void* __restrict__ ei)
{
    int e = blockIdx.x * blockDim.x + threadIdx.x;
    if (e >= N_EDGES) return;
    int t = clamp_node(load_idx(ei, (long long)N_EDGES + e));
    atomicAdd(&g_deg[t], 1);
}

__global__ __launch_bounds__(256) void csr_block_sum_kernel()
{
    __shared__ int sd[256];
    int t = blockIdx.x * 256 + threadIdx.x;
    int d = (t < N_NODES) ? g_deg[t] : 0;
    sd[threadIdx.x] = d;
    __syncthreads();
    for (int off = 128; off > 0; off >>= 1) {
        if (threadIdx.x < off) sd[threadIdx.x] += sd[threadIdx.x + off];
        __syncthreads();
    }
    if (threadIdx.x == 0) g_bsum[blockIdx.x] = sd[0];
}

__global__ __launch_bounds__(256) void csr_scan_small_kernel()
{
    __shared__ int s[256];
    int i = threadIdx.x;
    int v = (i < SCAN_BLOCKS) ? g_bsum[i] : 0;
    s[i] = v;
    __syncthreads();
    for (int off = 1; off < 256; off <<= 1) {
        int t = (i >= off) ? s[i - off] : 0;
        __syncthreads();
        s[i] += t;
        __syncthreads();
    }
    if (i < SCAN_BLOCKS) g_boff[i] = s[i] - v;
}

__global__ __launch_bounds__(256) void csr_write_kernel()
{
    __shared__ int s[256];
    int i = threadIdx.x;
    int t = blockIdx.x * 256 + i;
    int d = (t < N_NODES) ? g_deg[t] : 0;
    s[i] = d;
    __syncthreads();
    for (int off = 1; off < 256; off <<= 1) {
        int tv = (i >= off) ? s[i - off] : 0;
        __syncthreads();
        s[i] += tv;
        __syncthreads();
    }
    int excl = s[i] - d + g_boff[blockIdx.x];
    if (t < N_NODES) {
        g_rowptr[t] = excl;
        g_cursor[t] = excl;
        if (t == N_NODES - 1) g_rowptr[N_NODES] = N_EDGES;
    }
}

__global__ __launch_bounds__(256) void csr_scatter_kernel(
    const void* __restrict__ ei, const float* __restrict__ eattr)
{
    int e = blockIdx.x * blockDim.x + threadIdx.x;
    if (e >= N_EDGES) return;
    int s = clamp_node(load_idx(ei, e));
    int t = clamp_node(load_idx(ei, (long long)N_EDGES + e));
    int pos = atomicAdd(&g_cursor[t], 1);
    if (pos >= 0 && pos < N_EDGES) {
        g_csrc[pos] = s;
        g_ctgt[pos] = t;
        g_cea[pos] = eattr[e];
    }
}

// ---------------- HMMA (mma.sync) GEMM, 64-row tile, 2 CTA/SM -----------------
#define GS 136
#define TILE_A (64 * GS * 2)
#define TILE_BB (128 * GS * 2)
#define OFF_AH 0
#define OFF_AL (OFF_AH + TILE_A)
#define OFF_BH (OFF_AL + TILE_A)
#define OFF_BL (OFF_BH + TILE_BB)
#define OFF_BIAS (OFF_BL + TILE_BB)
#define SMEM_TOTAL (OFF_BIAS + 512 * 4)

#define MMA_BF16(c, a, b0, b1) \
    asm volatile("mma.sync.aligned.m16n8k16.row.col.f32.bf16.bf16.f32 " \
        "{%0,%1,%2,%3}, {%4,%5,%6,%7}, {%8,%9}, {%0,%1,%2,%3};" \
        : "+f"((c)[0]), "+f"((c)[1]), "+f"((c)[2]), "+f"((c)[3]) \
        : "r"((a)[0]), "r"((a)[1]), "r"((a)[2]), "r"((a)[3]), \
          "r"(b0), "r"(b1))

template <int ROWS>
__device__ __forceinline__ void ld_tile(__nv_bfloat16* __restrict__ dst,
                                        const __nv_bfloat16* __restrict__ src,
                                        int rows_valid)
{
    for (int i = threadIdx.x; i < ROWS * 16; i += 256) {
        int r = i >> 4;
        int c = (i & 15) * 8;
        uint4 v = make_uint4(0u, 0u, 0u, 0u);
        if (r < rows_valid) v = *(const uint4*)(src + (size_t)r * HID + c);
        *(uint4*)(dst + r * GS + c) = v;
    }
}

template <int NMAT, bool RELU, bool SPLIT, bool CLEAR>
__global__ __launch_bounds__(256, 2) void hmma_gemm(
    const __nv_bfloat16* __restrict__ Ahi, const __nv_bfloat16* __restrict__ Alo,
    const __nv_bfloat16* __restrict__ Whi, const __nv_bfloat16* __restrict__ Wlo,
    const float* __restrict__ b0p, const float* __restrict__ b1p,
    const float* __restrict__ b2p, const float* __restrict__ b3p,
    float* __restrict__ o0, float* __restrict__ o1,
    float* __restrict__ o2, float* __restrict__ o3,
    __nv_bfloat16* __restrict__ shi, __nv_bfloat16* __restrict__ slo, int M)
{
    extern __shared__ char smem[];
    __nv_bfloat16* sAh = (__nv_bfloat16*)(smem + OFF_AH);
    __nv_bfloat16* sAl = (__nv_bfloat16*)(smem + OFF_AL);
    __nv_bfloat16* sBh = (__nv_bfloat16*)(smem + OFF_BH);
    __nv_bfloat16* sBl = (__nv_bfloat16*)(smem + OFF_BL);
    float* bias_s = (float*)(smem + OFF_BIAS);

    const int tid = threadIdx.x;
    const int warp = tid >> 5;
    const int lane = tid & 31;
    const int g = lane >> 2;
    const int t = lane & 3;
    const int warpM = warp >> 2;
    const int warpN = warp & 3;
    const int m0 = blockIdx.x * 64;
    const int nbase = warpN * 32;

    if (tid < 128) {
        bias_s[tid] = b0p[tid];
        if (NMAT > 1) { bias_s[128 + tid] = b1p[tid];
                        bias_s[256 + tid] = b2p[tid];
                        bias_s[384 + tid] = b3p[tid]; }
    }
    int rb = M - m0; if (rb > 64) rb = 64; if (rb < 0) rb = 0;
    ld_tile<64>(sAh, Ahi + (size_t)m0 * HID, rb);
    ld_tile<64>(sAl, Alo + (size_t)m0 * HID, rb);

    if (CLEAR) {
        if (blockIdx.x == 0 && tid < HID) { g_bnsum[tid] = 0.f; g_bnsq[tid] = 0.f; }
    }

    float* const outs[4] = {o0, o1, o2, o3};

    for (int mat = 0; mat < NMAT; mat++) {
        __syncthreads();
        ld_tile<128>(sBh, Whi + (size_t)mat * HID * HID, 128);
        ld_tile<128>(sBl, Wlo + (size_t)mat * HID * HID, 128);
        __syncthreads();

        float acc[2][4][4];
#pragma unroll
        for (int mt = 0; mt < 2; mt++)
#pragma unroll
            for (int nt = 0; nt < 4; nt++)
#pragma unroll
                for (int i = 0; i < 4; i++) acc[mt][nt][i] = 0.f;

#pragma unroll
        for (int ks = 0; ks < 8; ks++) {
            const int kk = ks * 16 + t * 2;
            uint32_t ah[2][4], al[2][4];
#pragma unroll
            for (int mt = 0; mt < 2; mt++) {
                int r = warpM * 32 + mt * 16 + g;
                const __nv_bfloat16* ph = sAh + r * GS + kk;
                const __nv_bfloat16* pl = sAl + r * GS + kk;
                ah[mt][0] = *(const uint32_t*)(ph);
                ah[mt][1] = *(const uint32_t*)(ph + 8 * GS);
                ah[mt][2] = *(const uint32_t*)(ph + 8);
                ah[mt][3] = *(const uint32_t*)(ph + 8 * GS + 8);
                al[mt][0] = *(const uint32_t*)(pl);
                al[mt][1] = *(const uint32_t*)(pl + 8 * GS);
                al[mt][2] = *(const uint32_t*)(pl + 8);
                al[mt][3] = *(const uint32_t*)(pl + 8 * GS + 8);
            }
#pragma unroll
            for (int nt = 0; nt < 4; nt++) {
                int nr = nbase + nt * 8 + g;
                const __nv_bfloat16* pbh = sBh + nr * GS + kk;
                const __nv_bfloat16* pbl = sBl + nr * GS + kk;
                uint32_t bh0 = *(const uint32_t*)(pbh);
                uint32_t bh1 = *(const uint32_t*)(pbh + 8);
                uint32_t bl0 = *(const uint32_t*)(pbl);
                uint32_t bl1 = *(const uint32_t*)(pbl + 8);
#pragma unroll
                for (int mt = 0; mt < 2; mt++) {
                    MMA_BF16(acc[mt][nt], ah[mt], bh0, bh1);
                    MMA_BF16(acc[mt][nt], ah[mt], bl0, bl1);
                    MMA_BF16(acc[mt][nt], al[mt], bh0, bh1);
                }
            }
        }

        float* oP = outs[mat];
        const float* bs = bias_s + mat * 128;
#pragma unroll
        for (int mt = 0; mt < 2; mt++) {
#pragma unroll
            for (int nt = 0; nt < 4; nt++) {
                int r0 = m0 + warpM * 32 + mt * 16 + g;
                int c = nbase + nt * 8 + t * 2;
                float bv0 = bs[c], bv1 = bs[c + 1];
                float v0 = acc[mt][nt][0] + bv0;
                float v1 = acc[mt][nt][1] + bv1;
                float v2 = acc[mt][nt][2] + bv0;
                float v3 = acc[mt][nt][3] + bv1;
                if (RELU) {
                    v0 = fmaxf(v0, 0.f); v1 = fmaxf(v1, 0.f);
                    v2 = fmaxf(v2, 0.f); v3 = fmaxf(v3, 0.f);
                }
                if (r0 < M) {
                    *(float2*)(oP + (size_t)r0 * HID + c) = make_float2(v0, v1);
                    if (SPLIT) {
                        __nv_bfloat162 h2 = __floats2bfloat162_rn(v0, v1);
                        __nv_bfloat162 l2 = __floats2bfloat162_rn(
                            v0 - __bfloat162float(h2.x), v1 - __bfloat162float(h2.y));
                        *(__nv_bfloat162*)(shi + (size_t)r0 * HID + c) = h2;
                        *(__nv_bfloat162*)(slo + (size_t)r0 * HID + c) = l2;
                    }
                }
                int r1 = r0 + 8;
                if (r1 < M) {
                    *(float2*)(oP + (size_t)r1 * HID + c) = make_float2(v2, v3);
                    if (SPLIT) {
                        __nv_bfloat162 h2 = __floats2bfloat162_rn(v2, v3);
                        __nv_bfloat162 l2 = __floats2bfloat162_rn(
                            v2 - __bfloat162float(h2.x), v3 - __bfloat162float(h2.y));
                        *(__nv_bfloat162*)(shi + (size_t)r1 * HID + c) = h2;
                        *(__nv_bfloat162*)(slo + (size_t)r1 * HID + c) = l2;
                    }
                }
            }
        }
    }
}

// ---------------- attention pass 1: edge-parallel alpha (no atomics) ---------
__global__ __launch_bounds__(256) void alpha_kernel(const float* __restrict__ We)
{
    int e = (blockIdx.x * blockDim.x + threadIdx.x) >> 5;
    if (e >= N_EDGES) return;
    int lane = threadIdx.x & 31;
    int s = g_csrc[e];
    int t = g_ctgt[e];
    float ea = g_cea[e];

    float4 qv = *(const float4*)(g_q + (size_t)t * HID + lane * 4);
    float4 kv = *(const float4*)(g_k + (size_t)s * HID + lane * 4);
    float4 we = *(const float4*)(We + lane * 4);
    kv.x = fmaf(ea, we.x, kv.x); kv.y = fmaf(ea, we.y, kv.y);
    kv.z = fmaf(ea, we.z, kv.z); kv.w = fmaf(ea, we.w, kv.w);

    float d = qv.x * kv.x + qv.y * kv.y + qv.z * kv.z + qv.w * kv.w;
    d += __shfl_xor_sync(0xffffffffu, d, 1);
    d += __shfl_xor_sync(0xffffffffu, d, 2);
    d += __shfl_xor_sync(0xffffffffu, d, 4);
    d *= 0.17677669529663687f;            // 1/sqrt(32)

    if ((lane & 7) == 0) {
        int h = lane >> 3;
        g_alpha[h * N_EDGES + e] = d;     // head-major plane; read-only after
    }
}

// ---------------- attention pass 2: softmax + weighted sum + gate + BN -------
// Warp per node. Softmax stats computed inline from the read-only score plane
// (cheap scalar broadcast loads), then one gather loop with a pure-FMA chain.
__global__ __launch_bounds__(256) void agg3_kernel(
    const float* __restrict__ We, const float* __restrict__ Wb)
{
    __shared__ __align__(16) float wb[3 * HID];
    for (int i = threadIdx.x; i < 3 * HID; i += 256) wb[i] = Wb[i];
    __syncthreads();

    const int lane = threadIdx.x & 31;
    const int h = lane >> 3;
    const int gwarp = (blockIdx.x * 256 + threadIdx.x) >> 5;
    const int nwarps = (gridDim.x * 256) >> 5;

    float4 we4 = *(const float4*)(We + lane * 4);
    float4 w0 = *(const float4*)&wb[lane * 4];
    float4 w1 = *(const float4*)&wb[HID + lane * 4];
    float4 w2 = *(const float4*)&wb[2 * HID + lane * 4];
    const float* aplane = g_alpha + (size_t)h * N_EDGES;

    float s0 = 0.f, s1 = 0.f, s2 = 0.f, s3 = 0.f;
    float q0 = 0.f, q1 = 0.f, q2 = 0.f, q3 = 0.f;

    for (int n = gwarp; n < N_NODES; n += nwarps) {
        const int beg = g_rowptr[n];
        const int end = g_rowptr[n + 1];

        // softmax stats over this node's row (per head; lanes redundant)
        float m = -INFINITY;
        for (int j = beg; j < end; j++) m = fmaxf(m, aplane[j]);
        float den = 0.f;
        for (int j = beg; j < end; j++) den += __expf(aplane[j] - m);
        float inv = (beg < end) ? __fdividef(1.f, den) : 0.f;

        float4 acc = make_float4(0.f, 0.f, 0.f, 0.f);
        float a_nxt = 0.f, ea_nxt = 0.f;
        float4 v_nxt = make_float4(0.f, 0.f, 0.f, 0.f);
        if (beg < end) {
            int sn = g_csrc[beg];
            a_nxt = aplane[beg];
            ea_nxt = g_cea[beg];
            v_nxt = *(const float4*)(g_v + (size_t)sn * HID + lane * 4);
        }
        for (int j = beg; j < end; j++) {
            float aj = a_nxt, ea = ea_nxt;
            float4 vv = v_nxt;
            if (j + 1 < end) {
                int sn = g_csrc[j + 1];
                a_nxt = aplane[j + 1];
                ea_nxt = g_cea[j + 1];
                v_nxt = *(const float4*)(g_v + (size_t)sn * HID + lane * 4);
            }
            float w = __expf(aj - m) * inv;
            acc.x = fmaf(w, fmaf(ea, we4.x, vv.x), acc.x);
            acc.y = fmaf(w, fmaf(ea, we4.y, vv.y), acc.y);
            acc.z = fmaf(w, fmaf(ea, we4.z, vv.z), acc.z);
            acc.w = fmaf(w, fmaf(ea, we4.w, vv.w), acc.w);
        }
        float4 o = acc;

        float4 r = *(const float4*)(g_xr + (size_t)n * HID + lane * 4);
        float dx = o.x - r.x, dy = o.y - r.y, dz = o.z - r.z, dw = o.w - r.w;
        float p = o.x * w0.x + o.y * w0.y + o.z * w0.z + o.w * w0.w
                + r.x * w1.x + r.y * w1.y + r.z * w1.z + r.w * w1.w
                + dx * w2.x + dy * w2.y + dz * w2.z + dw * w2.w;
        p += __shfl_xor_sync(0xffffffffu, p, 1);
        p += __shfl_xor_sync(0xffffffffu, p, 2);
        p += __shfl_xor_sync(0xffffffffu, p, 4);
        p += __shfl_xor_sync(0xffffffffu, p, 8);
        p += __shfl_xor_sync(0xffffffffu, p, 16);
        float beta = __fdividef(1.f, 1.f + __expf(-p));
        float ob = 1.f - beta;
        float4 hn;
        hn.x = beta * r.x + ob * o.x;
        hn.y = beta * r.y + ob * o.y;
        hn.z = beta * r.z + ob * o.z;
        hn.w = beta * r.w + ob * o.w;
        *(float4*)(g_hnew + (size_t)n * HID + lane * 4) = hn;
        s0 += hn.x; s1 += hn.y; s2 += hn.z; s3 += hn.w;
        q0 += hn.x * hn.x; q1 += hn.y * hn.y; q2 += hn.z * hn.z; q3 += hn.w * hn.w;
    }
    atomicAdd(&g_bnsum[lane * 4 + 0], s0);
    atomicAdd(&g_bnsum[lane * 4 + 1], s1);
    atomicAdd(&g_bnsum[lane * 4 + 2], s2);
    atomicAdd(&g_bnsum[lane * 4 + 3], s3);
    atomicAdd(&g_bnsq[lane * 4 + 0], q0);
    atomicAdd(&g_bnsq[lane * 4 + 1], q1);
    atomicAdd(&g_bnsq[lane * 4 + 2], q2);
    atomicAdd(&g_bnsq[lane * 4 + 3], q3);
}

// ---------------- BN scale/bias finalize -------------------------------------
__global__ void bn_finalize_kernel(const float* __restrict__ gamma,
                                   const float* __restrict__ beta)
{
    int c = threadIdx.x;
    if (c < HID) {
        float inv_n = 1.f / (float)N_NODES;
        float mu = g_bnsum[c] * inv_n;
        float var = g_bnsq[c] * inv_n - mu * mu;
        float sc = gamma[c] * rsqrtf(var + 1e-5f);
        g_scale[c] = sc;
        g_bias[c] = beta[c] - mu * sc;
    }
}

// ---------------- BN apply + relu + residual (+ optional bf16 split) ---------
template <bool SPLIT>
__global__ __launch_bounds__(256) void bn_apply_kernel(float* __restrict__ dst)
{
    int i = blockIdx.x * blockDim.x + threadIdx.x;
    if (i >= N_NODES * (HID / 4)) return;
    int c4 = i & 31;
    float4 hn = *(const float4*)(g_hnew + (size_t)i * 4);
    float4 sc = *(const float4*)(g_scale + c4 * 4);
    float4 bi = *(const float4*)(g_bias + c4 * 4);
    float4 hr = *(const float4*)(g_h + (size_t)i * 4);
    float4 o;
    o.x = fmaxf(fmaf(hn.x, sc.x, bi.x), 0.f) + hr.x;
    o.y = fmaxf(fmaf(hn.y, sc.y, bi.y), 0.f) + hr.y;
    o.z = fmaxf(fmaf(hn.z, sc.z, bi.z), 0.f) + hr.z;
    o.w = fmaxf(fmaf(hn.w, sc.w, bi.w), 0.f) + hr.w;
    *(float4*)(dst + (size_t)i * 4) = o;
    if (SPLIT) {
        __nv_bfloat162 h0 = __floats2bfloat162_rn(o.x, o.y);
        __nv_bfloat162 h1 = __floats2bfloat162_rn(o.z, o.w);
        __nv_bfloat162 l0 = __floats2bfloat162_rn(o.x - __bfloat162float(h0.x),
                                                  o.y - __bfloat162float(h0.y));
        __nv_bfloat162 l1 = __floats2bfloat162_rn(o.z - __bfloat162float(h1.x),
                                                  o.w - __bfloat162float(h1.y));
        ((__nv_bfloat162*)g_ahi)[i * 2 + 0] = h0;
        ((__nv_bfloat162*)g_ahi)[i * 2 + 1] = h1;
        ((__nv_bfloat162*)g_alo)[i * 2 + 0] = l0;
        ((__nv_bfloat162*)g_alo)[i * 2 + 1] = l1;
    }
}

// ---------------- launch -----------------------------------------------------
extern "C" void kernel_launch(void* const* d_in, const int* in_sizes, int n_in,
                              void* d_out, int out_size)
{
    const float* x      = (const float*)d_in[0];
    const void*  ei     = d_in[1];
    const float* eattr  = (const float*)d_in[2];
    const float* W_in   = (const float*)d_in[3];
    const float* b_in   = (const float*)d_in[4];
    const float* Wq     = (const float*)d_in[5];
    const float* bq     = (const float*)d_in[6];
    const float* Wk     = (const float*)d_in[7];
    const float* bk     = (const float*)d_in[8];
    const float* Wv     = (const float*)d_in[9];
    const float* bv     = (const float*)d_in[10];
    const float* We     = (const float*)d_in[11];
    const float* Wskip  = (const float*)d_in[12];
    const float* bskip  = (const float*)d_in[13];
    const float* Wbeta  = (const float*)d_in[14];
    const float* bn_g   = (const float*)d_in[15];
    const float* bn_b   = (const float*)d_in[16];
    float* out = (float*)d_out;

    float *p_h, *p_q, *p_k, *p_v, *p_xr;
    __nv_bfloat16 *p_ahi, *p_alo, *p_whi, *p_wlo;
    cudaGetSymbolAddress((void**)&p_h, g_h);
    cudaGetSymbolAddress((void**)&p_q, g_q);
    cudaGetSymbolAddress((void**)&p_k, g_k);
    cudaGetSymbolAddress((void**)&p_v, g_v);
    cudaGetSymbolAddress((void**)&p_xr, g_xr);
    cudaGetSymbolAddress((void**)&p_ahi, g_ahi);
    cudaGetSymbolAddress((void**)&p_alo, g_alo);
    cudaGetSymbolAddress((void**)&p_whi, g_whi);
    cudaGetSymbolAddress((void**)&p_wlo, g_wlo);

    cudaFuncSetAttribute(hmma_gemm<1, true, true, false>,
                         cudaFuncAttributeMaxDynamicSharedMemorySize, SMEM_TOTAL);
    cudaFuncSetAttribute(hmma_gemm<4, false, false, true>,
                         cudaFuncAttributeMaxDynamicSharedMemorySize, SMEM_TOTAL);

    const int mma_grid   = (N_NODES + 63) / 64;          // 782
    const int edge_grid  = (N_EDGES + 255) / 256;        // 1250
    const int edge_wgrid = (N_EDGES * 32 + 255) / 256;   // 40000 (warp/edge)
    const int app_grid   = (N_NODES * (HID / 4) + 255) / 256;
    const size_t WM = (size_t)HID * HID;

    wsplit_all_kernel<<<9 * 64, 256>>>(W_in, Wq, Wk, Wv, Wskip, ei);
    xsplit_kernel<<<app_grid, 256>>>(x);
    csr_count_kernel<<<edge_grid, 256>>>(ei);
    csr_block_sum_kernel<<<SCAN_BLOCKS, 256>>>();
    csr_scan_small_kernel<<<1, 256>>>();
    csr_write_kernel<<<SCAN_BLOCKS, 256>>>();
    csr_scatter_kernel<<<edge_grid, 256>>>(ei, eattr);

    hmma_gemm<1, true, true, false><<<mma_grid, 256, SMEM_TOTAL>>>(
        p_ahi, p_alo, p_whi, p_wlo,
        b_in, b_in, b_in, b_in,
        p_h, p_h, p_h, p_h,
        p_ahi, p_alo, N_NODES);

    for (int l = 0; l < N_LAYERS; l++) {
        const float* We_l = We + (size_t)l * HID;

        hmma_gemm<4, false, false, true><<<mma_grid, 256, SMEM_TOTAL>>>(
            p_ahi, p_alo,
            p_whi + (size_t)(1 + 4 * l) * WM, p_wlo + (size_t)(1 + 4 * l) * WM,
            bq + l * HID, bk + l * HID, bv + l * HID, bskip + l * HID,
            p_q, p_k, p_v, p_xr,
            (__nv_bfloat16*)0, (__nv_bfloat16*)0, N_NODES);

        alpha_kernel<<<edge_wgrid, 256>>>(We_l);           // edge-parallel scores
        agg3_kernel<<<1184, 256>>>(We_l,                   // softmax + sum + gate + BN
                                   Wbeta + (size_t)l * 3 * HID);
        bn_finalize_kernel<<<1, 128>>>(bn_g + l * HID, bn_b + l * HID);
        if (l == N_LAYERS - 1)
            bn_apply_kernel<false><<<app_grid, 256>>>(out);
        else
            bn_apply_kernel<true><<<app_grid, 256>>>(p_h);
    }
}

// round 16
// speedup vs baseline: 1.6775x; 1.6775x over previous
#include <cuda_runtime.h>
#include <cuda_bf16.h>
#include <stdint.h>
#include <math.h>

#define N_NODES 50000
#define N_EDGES 320000
#define HID 128
#define HEADS 4
#define N_LAYERS 2

// ---------------- scratch (device globals; no allocations allowed) ----------
static __device__ __align__(16) float g_h[N_NODES * HID];
static __device__ __align__(16) float g_q[N_NODES * HID];
static __device__ __align__(16) float g_k[N_NODES * HID];
static __device__ __align__(16) float g_v[N_NODES * HID];
static __device__ __align__(16) float g_xr[N_NODES * HID];
static __device__ __align__(16) float g_out[N_NODES * HID];
static __device__ __align__(16) float g_hnew[N_NODES * HID];
static __device__ __align__(16) float g_alpha[N_EDGES * HEADS];
static __device__ __align__(16) unsigned g_amax[N_NODES * HEADS];
static __device__ __align__(16) float g_denom[N_NODES * HEADS];
static __device__ __align__(16) float g_bnsum[HID];
static __device__ __align__(16) float g_bnsq[HID];
static __device__ __align__(16) float g_scale[HID];
static __device__ __align__(16) float g_bias[HID];
static __device__ int g_idx64;
// bf16 hi/lo splits of the GEMM A operand (x, then h per layer)
static __device__ __align__(16) __nv_bfloat16 g_ahi[N_NODES * HID];
static __device__ __align__(16) __nv_bfloat16 g_alo[N_NODES * HID];
// bf16 hi/lo splits of transposed weights: [9][128 n][128 k]
// slot 0 = W_in ; 1+4l+{0,1,2,3} = Wq,Wk,Wv,Wskip of layer l
static __device__ __align__(16) __nv_bfloat16 g_whi[9 * HID * HID];
static __device__ __align__(16) __nv_bfloat16 g_wlo[9 * HID * HID];

// ---------------- helpers ----------------------------------------------------
__device__ __forceinline__ unsigned encf(float x) {
    unsigned u = __float_as_uint(x);
    return (u & 0x80000000u) ? ~u : (u | 0x80000000u);
}
__device__ __forceinline__ float decf(unsigned u) {
    return (u & 0x80000000u) ? __uint_as_float(u & 0x7fffffffu)
                             : __uint_as_float(~u);
}
__device__ __forceinline__ long long load_idx(const void* ei, long long i) {
    return g_idx64 ? ((const long long*)ei)[i] : (long long)((const int*)ei)[i];
}

// ---------------- fused weight split (all 9 mats) + idx detect ---------------
__global__ __launch_bounds__(256) void wsplit_all_kernel(
    const float* __restrict__ W_in, const float* __restrict__ Wq,
    const float* __restrict__ Wk, const float* __restrict__ Wv,
    const float* __restrict__ Wskip, const void* __restrict__ ei)
{
    if (blockIdx.x == 0 && threadIdx.x == 0) {
        const int* p = (const int*)ei;
        int all0 = 1;
        for (int i = 0; i < 32; i++)
            if (p[2 * i + 1] != 0) { all0 = 0; break; }
        g_idx64 = all0;
    }
    const int slot = blockIdx.x >> 6;                    // 64 blocks per slot
    const int idx = (blockIdx.x & 63) * 256 + threadIdx.x;
    if (idx >= HID * HID) return;
    const float* src;
    if (slot == 0) src = W_in;
    else {
        int l = (slot - 1) >> 2, m = (slot - 1) & 3;
        const float* bases[4] = {Wq, Wk, Wv, Wskip};
        src = bases[m] + (size_t)l * HID * HID;
    }
    int n = idx >> 7, k = idx & 127;
    float v = src[k * HID + n];
    __nv_bfloat16 hi = __float2bfloat16(v);
    float lo = v - __bfloat162float(hi);
    size_t o = (size_t)slot * HID * HID + idx;
    g_whi[o] = hi;
    g_wlo[o] = __float2bfloat16(lo);
}

__global__ __launch_bounds__(256) void xsplit_kernel(const float* __restrict__ x)
{
    int i = blockIdx.x * blockDim.x + threadIdx.x;   // float4 index
    if (i >= N_NODES * (HID / 4)) return;
    float4 v = *(const float4*)(x + (size_t)i * 4);
    __nv_bfloat162 h0 = __floats2bfloat162_rn(v.x, v.y);
    __nv_bfloat162 h1 = __floats2bfloat162_rn(v.z, v.w);
    __nv_bfloat162 l0 = __floats2bfloat162_rn(v.x - __bfloat162float(h0.x),
                                              v.y - __bfloat162float(h0.y));
    __nv_bfloat162 l1 = __floats2bfloat162_rn(v.z - __bfloat162float(h1.x),
                                              v.w - __bfloat162float(h1.y));
    ((__nv_bfloat162*)g_ahi)[i * 2 + 0] = h0;
    ((__nv_bfloat162*)g_ahi)[i * 2 + 1] = h1;
    ((__nv_bfloat162*)g_alo)[i * 2 + 0] = l0;
    ((__nv_bfloat162*)g_alo)[i * 2 + 1] = l1;
}

// ---------------- HMMA (mma.sync) GEMM, 64-row tile, 2 CTA/SM -----------------
// C[M,128] = A[M,128] @ B[128,128]^T(stored [n][k]) + bias, NMAT B mats share A.
// bf16x3 split: D = Ah*Bh + Ah*Bl + Al*Bh, fp32 accumulate.
// CLEAR: block clears its 64 rows of g_out/g_amax/g_denom; block 0 clears BN.
#define GS 136                         // smem row stride in bf16 (+8 pad)
#define TILE_A (64 * GS * 2)           // 17408
#define TILE_BB (128 * GS * 2)         // 34816
#define OFF_AH 0
#define OFF_AL (OFF_AH + TILE_A)
#define OFF_BH (OFF_AL + TILE_A)
#define OFF_BL (OFF_BH + TILE_BB)
#define OFF_BIAS (OFF_BL + TILE_BB)    // float[512]
#define SMEM_TOTAL (OFF_BIAS + 512 * 4)   // 106496 -> 2 CTAs/SM

#define MMA_BF16(c, a, b0, b1) \
    asm volatile("mma.sync.aligned.m16n8k16.row.col.f32.bf16.bf16.f32 " \
        "{%0,%1,%2,%3}, {%4,%5,%6,%7}, {%8,%9}, {%0,%1,%2,%3};" \
        : "+f"((c)[0]), "+f"((c)[1]), "+f"((c)[2]), "+f"((c)[3]) \
        : "r"((a)[0]), "r"((a)[1]), "r"((a)[2]), "r"((a)[3]), \
          "r"(b0), "r"(b1))

template <int ROWS>
__device__ __forceinline__ void ld_tile(__nv_bfloat16* __restrict__ dst,
                                        const __nv_bfloat16* __restrict__ src,
                                        int rows_valid)
{
    for (int i = threadIdx.x; i < ROWS * 16; i += 256) {   // uint4 granules
        int r = i >> 4;
        int c = (i & 15) * 8;
        uint4 v = make_uint4(0u, 0u, 0u, 0u);
        if (r < rows_valid) v = *(const uint4*)(src + (size_t)r * HID + c);
        *(uint4*)(dst + r * GS + c) = v;
    }
}

template <int NMAT, bool RELU, bool SPLIT, bool CLEAR>
__global__ __launch_bounds__(256, 2) void hmma_gemm(
    const __nv_bfloat16* __restrict__ Ahi, const __nv_bfloat16* __restrict__ Alo,
    const __nv_bfloat16* __restrict__ Whi, const __nv_bfloat16* __restrict__ Wlo,
    const float* __restrict__ b0p, const float* __restrict__ b1p,
    const float* __restrict__ b2p, const float* __restrict__ b3p,
    float* __restrict__ o0, float* __restrict__ o1,
    float* __restrict__ o2, float* __restrict__ o3,
    __nv_bfloat16* __restrict__ shi, __nv_bfloat16* __restrict__ slo, int M)
{
    extern __shared__ char smem[];
    __nv_bfloat16* sAh = (__nv_bfloat16*)(smem + OFF_AH);
    __nv_bfloat16* sAl = (__nv_bfloat16*)(smem + OFF_AL);
    __nv_bfloat16* sBh = (__nv_bfloat16*)(smem + OFF_BH);
    __nv_bfloat16* sBl = (__nv_bfloat16*)(smem + OFF_BL);
    float* bias_s = (float*)(smem + OFF_BIAS);

    const int tid = threadIdx.x;
    const int warp = tid >> 5;
    const int lane = tid & 31;
    const int g = lane >> 2;          // groupID 0..7
    const int t = lane & 3;           // threadID_in_group
    const int warpM = warp >> 2;      // 0..1 -> 32-row strip
    const int warpN = warp & 3;       // 0..3 -> 32-col strip
    const int m0 = blockIdx.x * 64;
    const int nbase = warpN * 32;

    if (tid < 128) {
        bias_s[tid] = b0p[tid];
        if (NMAT > 1) { bias_s[128 + tid] = b1p[tid];
                        bias_s[256 + tid] = b2p[tid];
                        bias_s[384 + tid] = b3p[tid]; }
    }
    int rb = M - m0; if (rb > 64) rb = 64; if (rb < 0) rb = 0;
    ld_tile<64>(sAh, Ahi + (size_t)m0 * HID, rb);
    ld_tile<64>(sAl, Alo + (size_t)m0 * HID, rb);

    if (CLEAR) {
        float4 z4 = make_float4(0.f, 0.f, 0.f, 0.f);
        for (int i = tid; i < rb * 32; i += 256)
            ((float4*)g_out)[(size_t)m0 * 32 + i] = z4;
        for (int i = tid; i < rb * HEADS; i += 256) {
            g_amax[m0 * HEADS + i] = 0u;
            g_denom[m0 * HEADS + i] = 0.f;
        }
        if (blockIdx.x == 0 && tid < HID) { g_bnsum[tid] = 0.f; g_bnsq[tid] = 0.f; }
    }

    float* const outs[4] = {o0, o1, o2, o3};

    for (int mat = 0; mat < NMAT; mat++) {
        __syncthreads();      // prior compute done before overwriting B
        ld_tile<128>(sBh, Whi + (size_t)mat * HID * HID, 128);
        ld_tile<128>(sBl, Wlo + (size_t)mat * HID * HID, 128);
        __syncthreads();

        float acc[2][4][4];
#pragma unroll
        for (int mt = 0; mt < 2; mt++)
#pragma unroll
            for (int nt = 0; nt < 4; nt++)
#pragma unroll
                for (int i = 0; i < 4; i++) acc[mt][nt][i] = 0.f;

#pragma unroll
        for (int ks = 0; ks < 8; ks++) {
            const int kk = ks * 16 + t * 2;
            uint32_t ah[2][4], al[2][4];
#pragma unroll
            for (int mt = 0; mt < 2; mt++) {
                int r = warpM * 32 + mt * 16 + g;
                const __nv_bfloat16* ph = sAh + r * GS + kk;
                const __nv_bfloat16* pl = sAl + r * GS + kk;
                ah[mt][0] = *(const uint32_t*)(ph);
                ah[mt][1] = *(const uint32_t*)(ph + 8 * GS);
                ah[mt][2] = *(const uint32_t*)(ph + 8);
                ah[mt][3] = *(const uint32_t*)(ph + 8 * GS + 8);
                al[mt][0] = *(const uint32_t*)(pl);
                al[mt][1] = *(const uint32_t*)(pl + 8 * GS);
                al[mt][2] = *(const uint32_t*)(pl + 8);
                al[mt][3] = *(const uint32_t*)(pl + 8 * GS + 8);
            }
#pragma unroll
            for (int nt = 0; nt < 4; nt++) {
                int nr = nbase + nt * 8 + g;
                const __nv_bfloat16* pbh = sBh + nr * GS + kk;
                const __nv_bfloat16* pbl = sBl + nr * GS + kk;
                uint32_t bh0 = *(const uint32_t*)(pbh);
                uint32_t bh1 = *(const uint32_t*)(pbh + 8);
                uint32_t bl0 = *(const uint32_t*)(pbl);
                uint32_t bl1 = *(const uint32_t*)(pbl + 8);
#pragma unroll
                for (int mt = 0; mt < 2; mt++) {
                    MMA_BF16(acc[mt][nt], ah[mt], bh0, bh1);
                    MMA_BF16(acc[mt][nt], ah[mt], bl0, bl1);
                    MMA_BF16(acc[mt][nt], al[mt], bh0, bh1);
                }
            }
        }

        // epilogue: bias (+relu) (+bf16 split) and store
        float* oP = outs[mat];
        const float* bs = bias_s + mat * 128;
#pragma unroll
        for (int mt = 0; mt < 2; mt++) {
#pragma unroll
            for (int nt = 0; nt < 4; nt++) {
                int r0 = m0 + warpM * 32 + mt * 16 + g;
                int c = nbase + nt * 8 + t * 2;
                float bv0 = bs[c], bv1 = bs[c + 1];
                float v0 = acc[mt][nt][0] + bv0;
                float v1 = acc[mt][nt][1] + bv1;
                float v2 = acc[mt][nt][2] + bv0;
                float v3 = acc[mt][nt][3] + bv1;
                if (RELU) {
                    v0 = fmaxf(v0, 0.f); v1 = fmaxf(v1, 0.f);
                    v2 = fmaxf(v2, 0.f); v3 = fmaxf(v3, 0.f);
                }
                if (r0 < M) {
                    *(float2*)(oP + (size_t)r0 * HID + c) = make_float2(v0, v1);
                    if (SPLIT) {
                        __nv_bfloat162 h2 = __floats2bfloat162_rn(v0, v1);
                        __nv_bfloat162 l2 = __floats2bfloat162_rn(
                            v0 - __bfloat162float(h2.x), v1 - __bfloat162float(h2.y));
                        *(__nv_bfloat162*)(shi + (size_t)r0 * HID + c) = h2;
                        *(__nv_bfloat162*)(slo + (size_t)r0 * HID + c) = l2;
                    }
                }
                int r1 = r0 + 8;
                if (r1 < M) {
                    *(float2*)(oP + (size_t)r1 * HID + c) = make_float2(v2, v3);
                    if (SPLIT) {
                        __nv_bfloat162 h2 = __floats2bfloat162_rn(v2, v3);
                        __nv_bfloat162 l2 = __floats2bfloat162_rn(
                            v2 - __bfloat162float(h2.x), v3 - __bfloat162float(h2.y));
                        *(__nv_bfloat162*)(shi + (size_t)r1 * HID + c) = h2;
                        *(__nv_bfloat162*)(slo + (size_t)r1 * HID + c) = l2;
                    }
                }
            }
        }
    }
}

// ---------------- edge pass 1: alpha + segment max ---------------------------
__global__ __launch_bounds__(256) void edge_alpha_kernel(
    const void* __restrict__ ei, const float* __restrict__ eattr,
    const float* __restrict__ We)
{
    int e = (blockIdx.x * blockDim.x + threadIdx.x) >> 5;
    if (e >= N_EDGES) return;
    int lane = threadIdx.x & 31;
    long long s = load_idx(ei, e);
    long long t = load_idx(ei, (long long)N_EDGES + e);

    float4 qv = *(const float4*)(g_q + t * HID + lane * 4);
    float4 kv = *(const float4*)(g_k + s * HID + lane * 4);
    float ea = eattr[e];
    float4 we = *(const float4*)(We + lane * 4);
    kv.x = fmaf(ea, we.x, kv.x); kv.y = fmaf(ea, we.y, kv.y);
    kv.z = fmaf(ea, we.z, kv.z); kv.w = fmaf(ea, we.w, kv.w);

    float d = qv.x * kv.x + qv.y * kv.y + qv.z * kv.z + qv.w * kv.w;
    d += __shfl_xor_sync(0xffffffffu, d, 1);
    d += __shfl_xor_sync(0xffffffffu, d, 2);
    d += __shfl_xor_sync(0xffffffffu, d, 4);
    d *= 0.17677669529663687f;            // 1/sqrt(32)

    if ((lane & 7) == 0) {
        int h = lane >> 3;
        g_alpha[e * HEADS + h] = d;
        atomicMax(&g_amax[t * HEADS + h], encf(d));
    }
}

// ---------------- edge pass 2: exp + denom + unnormalized message agg --------
__global__ __launch_bounds__(256) void edge_msg_kernel(
    const void* __restrict__ ei, const float* __restrict__ eattr,
    const float* __restrict__ We)
{
    int e = (blockIdx.x * blockDim.x + threadIdx.x) >> 5;
    if (e >= N_EDGES) return;
    int lane = threadIdx.x & 31;
    int h = lane >> 3;
    long long s = load_idx(ei, e);
    long long t = load_idx(ei, (long long)N_EDGES + e);

    float m = decf(g_amax[t * HEADS + h]);
    float ex = __expf(g_alpha[e * HEADS + h] - m);
    if ((lane & 7) == 0)
        atomicAdd(&g_denom[t * HEADS + h], ex);

    float4 vv = *(const float4*)(g_v + s * HID + lane * 4);
    float ea = eattr[e];
    float4 we = *(const float4*)(We + lane * 4);
    vv.x = fmaf(ea, we.x, vv.x); vv.y = fmaf(ea, we.y, vv.y);
    vv.z = fmaf(ea, we.z, vv.z); vv.w = fmaf(ea, we.w, vv.w);

    float mx = vv.x * ex, my = vv.y * ex, mz = vv.z * ex, mw = vv.w * ex;
    float* dst = g_out + t * HID + lane * 4;
    asm volatile("red.global.add.v4.f32 [%0], {%1,%2,%3,%4};"
                 :: "l"(dst), "f"(mx), "f"(my), "f"(mz), "f"(mw) : "memory");
}

// ---------------- beta gate + h_new + BN partial stats -----------------------
// g_out holds unnormalized sums; divide by denom here (0-in-degree -> 0).
__global__ __launch_bounds__(256) void combine_kernel(const float* __restrict__ Wb)
{
    __shared__ __align__(16) float wb[3 * HID];
    for (int i = threadIdx.x; i < 3 * HID; i += blockDim.x) wb[i] = Wb[i];
    __syncthreads();

    int lane = threadIdx.x & 31;
    int head = lane >> 3;
    int warp = (blockIdx.x * blockDim.x + threadIdx.x) >> 5;
    int nwarps = (gridDim.x * blockDim.x) >> 5;

    float4 w0 = *(const float4*)&wb[lane * 4];
    float4 w1 = *(const float4*)&wb[HID + lane * 4];
    float4 w2 = *(const float4*)&wb[2 * HID + lane * 4];

    float s0 = 0.f, s1 = 0.f, s2 = 0.f, s3 = 0.f;
    float q0 = 0.f, q1 = 0.f, q2 = 0.f, q3 = 0.f;

    for (int n = warp; n < N_NODES; n += nwarps) {
        float den = g_denom[(size_t)n * HEADS + head];
        float inv = (den != 0.f) ? __fdividef(1.f, den) : 0.f;
        float4 o = *(const float4*)(g_out + (size_t)n * HID + lane * 4);
        o.x *= inv; o.y *= inv; o.z *= inv; o.w *= inv;
        float4 r = *(const float4*)(g_xr + (size_t)n * HID + lane * 4);
        float dx = o.x - r.x, dy = o.y - r.y, dz = o.z - r.z, dw = o.w - r.w;
        float p = o.x * w0.x + o.y * w0.y + o.z * w0.z + o.w * w0.w
                + r.x * w1.x + r.y * w1.y + r.z * w1.z + r.w * w1.w
                + dx * w2.x + dy * w2.y + dz * w2.z + dw * w2.w;
        p += __shfl_xor_sync(0xffffffffu, p, 1);
        p += __shfl_xor_sync(0xffffffffu, p, 2);
        p += __shfl_xor_sync(0xffffffffu, p, 4);
        p += __shfl_xor_sync(0xffffffffu, p, 8);
        p += __shfl_xor_sync(0xffffffffu, p, 16);
        float beta = __fdividef(1.f, 1.f + __expf(-p));
        float ob = 1.f - beta;
        float4 hn;
        hn.x = beta * r.x + ob * o.x;
        hn.y = beta * r.y + ob * o.y;
        hn.z = beta * r.z + ob * o.z;
        hn.w = beta * r.w + ob * o.w;
        *(float4*)(g_hnew + (size_t)n * HID + lane * 4) = hn;
        s0 += hn.x; s1 += hn.y; s2 += hn.z; s3 += hn.w;
        q0 += hn.x * hn.x; q1 += hn.y * hn.y; q2 += hn.z * hn.z; q3 += hn.w * hn.w;
    }
    atomicAdd(&g_bnsum[lane * 4 + 0], s0);
    atomicAdd(&g_bnsum[lane * 4 + 1], s1);
    atomicAdd(&g_bnsum[lane * 4 + 2], s2);
    atomicAdd(&g_bnsum[lane * 4 + 3], s3);
    atomicAdd(&g_bnsq[lane * 4 + 0], q0);
    atomicAdd(&g_bnsq[lane * 4 + 1], q1);
    atomicAdd(&g_bnsq[lane * 4 + 2], q2);
    atomicAdd(&g_bnsq[lane * 4 + 3], q3);
}

// ---------------- BN scale/bias finalize -------------------------------------
__global__ void bn_finalize_kernel(const float* __restrict__ gamma,
                                   const float* __restrict__ beta)
{
    int c = threadIdx.x;
    if (c < HID) {
        float inv_n = 1.f / (float)N_NODES;
        float mu = g_bnsum[c] * inv_n;
        float var = g_bnsq[c] * inv_n - mu * mu;
        float sc = gamma[c] * rsqrtf(var + 1e-5f);
        g_scale[c] = sc;
        g_bias[c] = beta[c] - mu * sc;
    }
}

// ---------------- BN apply + relu + residual (+ optional bf16 split) ---------
template <bool SPLIT>
__global__ __launch_bounds__(256) void bn_apply_kernel(float* __restrict__ dst)
{
    int i = blockIdx.x * blockDim.x + threadIdx.x;   // one float4 each
    if (i >= N_NODES * (HID / 4)) return;
    int c4 = i & 31;
    float4 hn = *(const float4*)(g_hnew + (size_t)i * 4);
    float4 sc = *(const float4*)(g_scale + c4 * 4);
    float4 bi = *(const float4*)(g_bias + c4 * 4);
    float4 hr = *(const float4*)(g_h + (size_t)i * 4);
    float4 o;
    o.x = fmaxf(fmaf(hn.x, sc.x, bi.x), 0.f) + hr.x;
    o.y = fmaxf(fmaf(hn.y, sc.y, bi.y), 0.f) + hr.y;
    o.z = fmaxf(fmaf(hn.z, sc.z, bi.z), 0.f) + hr.z;
    o.w = fmaxf(fmaf(hn.w, sc.w, bi.w), 0.f) + hr.w;
    *(float4*)(dst + (size_t)i * 4) = o;
    if (SPLIT) {
        __nv_bfloat162 h0 = __floats2bfloat162_rn(o.x, o.y);
        __nv_bfloat162 h1 = __floats2bfloat162_rn(o.z, o.w);
        __nv_bfloat162 l0 = __floats2bfloat162_rn(o.x - __bfloat162float(h0.x),
                                                  o.y - __bfloat162float(h0.y));
        __nv_bfloat162 l1 = __floats2bfloat162_rn(o.z - __bfloat162float(h1.x),
                                                  o.w - __bfloat162float(h1.y));
        ((__nv_bfloat162*)g_ahi)[i * 2 + 0] = h0;
        ((__nv_bfloat162*)g_ahi)[i * 2 + 1] = h1;
        ((__nv_bfloat162*)g_alo)[i * 2 + 0] = l0;
        ((__nv_bfloat162*)g_alo)[i * 2 + 1] = l1;
    }
}

// ---------------- launch -----------------------------------------------------
extern "C" void kernel_launch(void* const* d_in, const int* in_sizes, int n_in,
                              void* d_out, int out_size)
{
    const float* x      = (const float*)d_in[0];
    const void*  ei     = d_in[1];
    const float* eattr  = (const float*)d_in[2];
    const float* W_in   = (const float*)d_in[3];
    const float* b_in   = (const float*)d_in[4];
    const float* Wq     = (const float*)d_in[5];
    const float* bq     = (const float*)d_in[6];
    const float* Wk     = (const float*)d_in[7];
    const float* bk     = (const float*)d_in[8];
    const float* Wv     = (const float*)d_in[9];
    const float* bv     = (const float*)d_in[10];
    const float* We     = (const float*)d_in[11];
    const float* Wskip  = (const float*)d_in[12];
    const float* bskip  = (const float*)d_in[13];
    const float* Wbeta  = (const float*)d_in[14];
    const float* bn_g   = (const float*)d_in[15];
    const float* bn_b   = (const float*)d_in[16];
    float* out = (float*)d_out;

    float *p_h, *p_q, *p_k, *p_v, *p_xr;
    __nv_bfloat16 *p_ahi, *p_alo, *p_whi, *p_wlo;
    cudaGetSymbolAddress((void**)&p_h, g_h);
    cudaGetSymbolAddress((void**)&p_q, g_q);
    cudaGetSymbolAddress((void**)&p_k, g_k);
    cudaGetSymbolAddress((void**)&p_v, g_v);
    cudaGetSymbolAddress((void**)&p_xr, g_xr);
    cudaGetSymbolAddress((void**)&p_ahi, g_ahi);
    cudaGetSymbolAddress((void**)&p_alo, g_alo);
    cudaGetSymbolAddress((void**)&p_whi, g_whi);
    cudaGetSymbolAddress((void**)&p_wlo, g_wlo);

    cudaFuncSetAttribute(hmma_gemm<1, true, true, false>,
                         cudaFuncAttributeMaxDynamicSharedMemorySize, SMEM_TOTAL);
    cudaFuncSetAttribute(hmma_gemm<4, false, false, true>,
                         cudaFuncAttributeMaxDynamicSharedMemorySize, SMEM_TOTAL);

    const int mma_grid   = (N_NODES + 63) / 64;          // 782
    const int edge_wgrid = (N_EDGES * 32 + 255) / 256;   // 40000
    const int app_grid   = (N_NODES * (HID / 4) + 255) / 256;
    const size_t WM = (size_t)HID * HID;

    // all 9 weight splits + int64/int32 index detection, one launch
    wsplit_all_kernel<<<9 * 64, 256>>>(W_in, Wq, Wk, Wv, Wskip, ei);
    xsplit_kernel<<<app_grid, 256>>>(x);

    // h = relu(x @ W_in + b_in); epilogue also writes h's bf16 split
    hmma_gemm<1, true, true, false><<<mma_grid, 256, SMEM_TOTAL>>>(
        p_ahi, p_alo, p_whi, p_wlo,
        b_in, b_in, b_in, b_in,
        p_h, p_h, p_h, p_h,
        p_ahi, p_alo, N_NODES);

    for (int l = 0; l < N_LAYERS; l++) {
        const float* We_l = We + (size_t)l * HID;

        // q,k,v,xr in one fused kernel; also clears g_out/amax/denom/BN stats
        hmma_gemm<4, false, false, true><<<mma_grid, 256, SMEM_TOTAL>>>(
            p_ahi, p_alo,
            p_whi + (size_t)(1 + 4 * l) * WM, p_wlo + (size_t)(1 + 4 * l) * WM,
            bq + l * HID, bk + l * HID, bv + l * HID, bskip + l * HID,
            p_q, p_k, p_v, p_xr,
            (__nv_bfloat16*)0, (__nv_bfloat16*)0, N_NODES);

        edge_alpha_kernel<<<edge_wgrid, 256>>>(ei, eattr, We_l);
        edge_msg_kernel<<<edge_wgrid, 256>>>(ei, eattr, We_l);

        combine_kernel<<<592, 256>>>(Wbeta + (size_t)l * 3 * HID);
        bn_finalize_kernel<<<1, 128>>>(bn_g + l * HID, bn_b + l * HID);
        if (l == N_LAYERS - 1)
            bn_apply_kernel<false><<<app_grid, 256>>>(out);
        else
            bn_apply_kernel<true><<<app_grid, 256>>>(p_h);
    }
}